// round 16
// baseline (speedup 1.0000x reference)
#include <cuda_runtime.h>
#include <cuda_bf16.h>

// TGSM v16: v15 with CH 16->8 (smem ~19KB) and __launch_bounds__(128,8) for
// 8 CTAs/SM occupancy. Single task round per chunk. Zero global scratch.
// B=1024, T=256, N=14, Fd=4, H=32, K=5, C=2

#define Bn 1024
#define Tn 256
#define Nn 14
#define Hn 32
#define CH 8           // chunk length (t steps per chunk)
#define RS 20          // row stride (floats) in the esm matrix

__device__ __forceinline__ float warp_sum(float v) {
    v += __shfl_xor_sync(0xffffffffu, v, 16);
    v += __shfl_xor_sync(0xffffffffu, v, 8);
    v += __shfl_xor_sync(0xffffffffu, v, 4);
    v += __shfl_xor_sync(0xffffffffu, v, 2);
    v += __shfl_xor_sync(0xffffffffu, v, 1);
    return v;
}
__device__ __forceinline__ float elu(float y) {
    return (y > 0.0f) ? y : (__expf(y) - 1.0f);
}
__device__ __forceinline__ float sigmoid_fast(float x) {
    float th;
    asm("tanh.approx.f32 %0, %1;" : "=f"(th) : "f"(0.5f * x));
    return fmaf(0.5f, th, 0.5f);
}
// map edge index e (0..90) to pair (n<m), row-major over upper triangle
__device__ __forceinline__ void edge_map(int e, int& n_, int& m_) {
    int n = 0, r = e, rl = 13;
    while (n < 13 && r >= rl) { r -= rl; rl--; n++; }
    n_ = n; m_ = n + 1 + r;
}

__global__ __launch_bounds__(128, 8)
void tgsm_fused(const float* __restrict__ ws,
                const float* __restrict__ gate_w, const float* __restrict__ gate_b,
                const float* __restrict__ gcn_w,  const float* __restrict__ gcn_b,
                const float* __restrict__ ln_g,   const float* __restrict__ ln_b,
                const float* __restrict__ attn_w, const float* __restrict__ attn_b,
                const float* __restrict__ c1_w,   const float* __restrict__ c1_b,
                const float* __restrict__ c2_w,   const float* __restrict__ c2_b,
                const float* __restrict__ c3_w,   const float* __restrict__ c3_b,
                float* __restrict__ out)
{
    const int b    = blockIdx.x;
    const int tid  = threadIdx.x;
    const int lane = tid & 31;
    const int warp = tid >> 5;
    const int half = lane >> 4;    // dual-task half
    const int c    = lane & 15;    // node index within half
    const int cc   = (c < 14) ? c : 0;

    __shared__ __align__(16) float4 s_nrm[CH][17];       // padded
    __shared__ float  s_len[CH][16];
    __shared__ __align__(16) float s_esmF[CH][Nn * RS];  // full sym matrices
    __shared__ __align__(16) float4 s_q[4][2][16];
    __shared__ float  s_dis[4][2][16];
    __shared__ float4 s_xp[4][2][17];                     // padded
    __shared__ float2 s_mr[4][2][17];                     // padded
    __shared__ float  s_G[25];
    __shared__ float  s_SWb[5];
    __shared__ float  s_pool[4][Hn];
    __shared__ float2 s_MS[4];
    __shared__ float2 s_cs[7];
    __shared__ int2   s_pq[7];
    __shared__ float  s_comb[5 + Hn];
    __shared__ float  s_b1[64];

    // constants (all warps run all phases)
    const float gw0 = gate_w[0], gw1 = gate_w[1], gbv = gate_b[0];
    const float Wc0 = gcn_w[0*Hn + lane];
    const float Wc1 = gcn_w[1*Hn + lane];
    const float Wc2 = gcn_w[2*Hn + lane];
    const float Wc3 = gcn_w[3*Hn + lane];
    const float gcnb = gcn_b[lane];
    const float lng = ln_g[lane], lnb = ln_b[lane];
    const float awv = attn_w[lane], attnb = attn_b[0];

    if (warp == 0) {
        float vW[5] = {Wc0, Wc1, Wc2, Wc3, gcnb};
        #pragma unroll
        for (int i2 = 0; i2 < 5; i2++) {
            #pragma unroll
            for (int j2 = i2; j2 < 5; j2++) {
                float g = warp_sum(vW[i2] * vW[j2]);
                if (lane == 0) { s_G[i2*5+j2] = g; s_G[j2*5+i2] = g; }
            }
            float sw = warp_sum(vW[i2]);
            if (lane == 0) s_SWb[i2] = sw;
        }
    }
    // zero ALL CH*Nn (=112) diagonal entries ONCE (never overwritten after)
    if (tid < CH * Nn) {
        int k2 = tid / Nn, d = tid - k2 * Nn;
        s_esmF[k2][d * (RS + 1)] = 0.0f;
    }

    // recurrence edge (tid-based)
    int rn = 0, rm = 1;
    const bool ract = (tid < 91);
    if (ract) edge_map(tid, rn, rm);
    float ee = 0.0f;

    // per-warp online softmax state (lane = channel)
    float Pol = 0.0f, Mol = -1e30f, Sol = 0.0f;

    const float4* src = reinterpret_cast<const float4*>(ws) + (size_t)b * (Tn * Nn);

    for (int ch = 0; ch < Tn / CH; ch++) {
        const int t0 = ch * CH;
        __syncthreads();     // protects s_nrm/s_esmF reuse (+ s_G/diag first iter)

        // ---- cooperative load + normalize: CH steps x 14 nodes (112 <= 128) ----
        if (tid < CH * Nn) {
            float4 v = src[t0 * Nn + tid];
            float d2 = v.x*v.x + v.y*v.y + v.z*v.z + v.w*v.w;
            float inv = rsqrtf(fmaxf(d2, 1e-24f));
            int tl2 = tid / 14;
            int nd  = tid - tl2 * 14;
            s_nrm[tl2][nd] = make_float4(v.x*inv, v.y*inv, v.z*inv, v.w*inv);
            s_len[tl2][nd] = d2 * inv;   // = |de|
        }
        __syncthreads();

        // ---- edge recurrence: CH steps, write symmetric matrix ----
        if (ract) {
            #pragma unroll
            for (int k = 0; k < CH; k++) {
                float4 a  = s_nrm[k][rn];
                float4 c4 = s_nrm[k][rm];
                float dot = a.x * c4.x;
                dot = fmaf(a.y, c4.y, dot);
                dot = fmaf(a.z, c4.z, dot);
                dot = fmaf(a.w, c4.w, dot);
                float adj = fmaf(dot, 0.5f, 0.5f);
                float xg = fmaf(gw0, ee, fmaf(gw1, adj, gbv));
                float z  = sigmoid_fast(xg);
                ee = fmaf(z, adj - ee, ee);
                s_esmF[k][rn * RS + rm] = ee;
                s_esmF[k][rm * RS + rn] = ee;
            }
        }
        __syncthreads();

        // ---- task round: 8 tasks (4 warps x 2 halves), merged A+B phase ----
        {
            const int tl = 2 * warp + half;
            const float* rowp = &s_esmF[tl][cc * RS];
            const bool act = (c < 14);

            // load row ONCE (vectorized, conflict-free) into registers
            float4 e0 = *reinterpret_cast<const float4*>(rowp);
            float4 e1 = *reinterpret_cast<const float4*>(rowp + 4);
            float4 e2 = *reinterpret_cast<const float4*>(rowp + 8);
            float2 e3 = *reinterpret_cast<const float2*>(rowp + 12);
            float er[14] = {e0.x,e0.y,e0.z,e0.w, e1.x,e1.y,e1.z,e1.w,
                            e2.x,e2.y,e2.z,e2.w, e3.x,e3.y};

            // rowsum -> dis, q ; publish for the matvec broadcast
            float rs = 1.0f;
            #pragma unroll
            for (int m3 = 0; m3 < 14; m3++) rs += er[m3];
            float dis = rsqrtf(fmaxf(rs, 1e-6f));
            float4 nr = s_nrm[tl][cc];
            float f = s_len[tl][cc] * dis;
            float4 qreg = make_float4(nr.x*f, nr.y*f, nr.z*f, nr.w*f);
            if (act) {
                s_q[warp][half][c]   = qreg;
                s_dis[warp][half][c] = dis;
            }
            __syncwarp();

            // matvec from shared broadcasts (serves both tasks per issue)
            float4 p = make_float4(0.f,0.f,0.f,0.f);
            float racc = 0.0f;
            #pragma unroll
            for (int m3 = 0; m3 < 14; m3++) {
                float4 qm = s_q[warp][half][m3];
                float dm  = s_dis[warp][half][m3];
                float em  = er[m3];
                p.x = fmaf(em, qm.x, p.x);
                p.y = fmaf(em, qm.y, p.y);
                p.z = fmaf(em, qm.z, p.z);
                p.w = fmaf(em, qm.w, p.w);
                racc = fmaf(em, dm, racc);
            }

            // LN stats (closed form) + publish xp/mr
            if (act) {
                float rr = dis * (racc + dis);
                float x0 = (p.x + qreg.x) * dis;
                float x1 = (p.y + qreg.y) * dis;
                float x2 = (p.z + qreg.z) * dis;
                float x3 = (p.w + qreg.w) * dis;
                float mu = (x0*s_SWb[0] + x1*s_SWb[1] + x2*s_SWb[2]
                          + x3*s_SWb[3] + rr*s_SWb[4]) * (1.0f/32.0f);
                float xt[5] = {x0, x1, x2, x3, rr};
                float s2 = 0.0f;
                #pragma unroll
                for (int ii = 0; ii < 5; ii++) {
                    float rowd = 0.0f;
                    #pragma unroll
                    for (int jj = 0; jj < 5; jj++)
                        rowd = fmaf(s_G[ii*5+jj], xt[jj], rowd);
                    s2 = fmaf(xt[ii], rowd, s2);
                }
                s2 *= (1.0f/32.0f);
                float var  = fmaf(-mu, mu, s2);
                float istd = rsqrtf(var + 1e-5f);
                s_xp[warp][half][c] = make_float4(x0*istd, x1*istd, x2*istd, x3*istd);
                s_mr[warp][half][c] = make_float2(rr*istd, mu*istd);
            }
            __syncwarp();

            // phase C: LN apply + ELU + node mean, BOTH tasks (full warp, ILP 2)
            float acc0 = 0.0f, acc1 = 0.0f;
            #pragma unroll
            for (int nq = 0; nq < 14; nq++) {
                float4 xa = s_xp[warp][0][nq];
                float2 ma = s_mr[warp][0][nq];
                float4 xb = s_xp[warp][1][nq];
                float2 mb = s_mr[warp][1][nq];
                float ha = -ma.y;
                ha = fmaf(xa.x, Wc0, ha);
                ha = fmaf(xa.y, Wc1, ha);
                ha = fmaf(xa.z, Wc2, ha);
                ha = fmaf(xa.w, Wc3, ha);
                ha = fmaf(ma.x, gcnb, ha);
                acc0 += elu(fmaf(ha, lng, lnb));
                float hb = -mb.y;
                hb = fmaf(xb.x, Wc0, hb);
                hb = fmaf(xb.y, Wc1, hb);
                hb = fmaf(xb.z, Wc2, hb);
                hb = fmaf(xb.w, Wc3, hb);
                acc1 += elu(fmaf(fmaf(mb.x, gcnb, hb), lng, lnb));
            }
            float ge0 = acc0 * (1.0f / 14.0f);
            float ge1 = acc1 * (1.0f / 14.0f);

            // merged dual-score online softmax update (exact)
            float r0 = warp_sum(ge0 * awv);
            float r1 = warp_sum(ge1 * awv);
            float sc0 = r0 + attnb, sc1 = r1 + attnb;
            float nM = fmaxf(Mol, fmaxf(sc0, sc1));
            float al = __expf(Mol - nM);
            float w0 = __expf(sc0 - nM);
            float w1 = __expf(sc1 - nM);
            Pol = fmaf(Pol, al, fmaf(w0, ge0, w1 * ge1));
            Sol = fmaf(Sol, al, w0 + w1);
            Mol = nM;
            __syncwarp();
        }
    }

    // ---- publish per-warp pool state ----
    s_pool[warp][lane] = Pol;
    if (lane == 0) s_MS[warp] = make_float2(Mol, Sol);
    __syncthreads();
    // final esm matrix: s_esmF[CH-1] (t=255), symmetric, zero diag. Ready.

    if (warp == 0) {
        // ---- combine 4 online-softmax partials (exact) ----
        float2 ms0 = s_MS[0], ms1 = s_MS[1], ms2 = s_MS[2], ms3 = s_MS[3];
        float M = fmaxf(fmaxf(ms0.x, ms1.x), fmaxf(ms2.x, ms3.x));
        float f0 = __expf(ms0.x - M), f1 = __expf(ms1.x - M);
        float f2 = __expf(ms2.x - M), f3 = __expf(ms3.x - M);
        float P = s_pool[0][lane]*f0 + s_pool[1][lane]*f1
                + s_pool[2][lane]*f2 + s_pool[3][lane]*f3;
        float S = ms0.y*f0 + ms1.y*f1 + ms2.y*f2 + ms3.y*f3;
        s_comb[5 + lane] = __fdividef(P, S);
    } else if (warp == 3) {
        // ---- warp-local parallel Jacobi on s_esmF[CH-1]: 6 sweeps ----
        float* sf = s_esmF[CH - 1];
        int rowi[4], kki[4];
        #pragma unroll
        for (int ii = 0; ii < 4; ii++) {
            int idx = lane + 32 * ii;
            rowi[ii] = idx / 7;
            kki[ii]  = idx - rowi[ii] * 7;
        }
        for (int sweep = 0; sweep < 6; sweep++) {
            for (int r = 0; r < 13; r++) {
                if (lane < 7) {
                    int pj = (lane == 0) ? 0 : 1 + (lane - 1 + r) % 13;
                    int qj = 1 + (12 - lane + r) % 13;
                    float apq = sf[pj*RS + qj];
                    float app = sf[pj*(RS+1)];
                    float aqq = sf[qj*(RS+1)];
                    float ap  = fabsf(apq);
                    float den = (ap > 1e-20f) ? apq : 1.0f;
                    float theta = __fdividef(0.5f * (aqq - app), den);
                    float tt = __fdividef(1.0f, fabsf(theta) + sqrtf(fmaf(theta, theta, 1.0f)));
                    tt = (theta < 0.0f) ? -tt : tt;
                    tt = (ap > 1e-20f) ? tt : 0.0f;
                    float cqq = rsqrtf(fmaf(tt, tt, 1.0f));
                    s_cs[lane] = make_float2(cqq, tt * cqq);
                    s_pq[lane] = make_int2(pj, qj);
                }
                __syncwarp();
                #pragma unroll
                for (int ii = 0; ii < 4; ii++) {
                    int idx = lane + 32 * ii;
                    if (idx < 98) {
                        float2 cs = s_cs[kki[ii]];
                        int2   pq = s_pq[kki[ii]];
                        int row = rowi[ii];
                        float a1 = sf[row*RS + pq.x];
                        float a2 = sf[row*RS + pq.y];
                        sf[row*RS + pq.x] = cs.x * a1 - cs.y * a2;
                        sf[row*RS + pq.y] = fmaf(cs.y, a1, cs.x * a2);
                    }
                }
                __syncwarp();
                #pragma unroll
                for (int ii = 0; ii < 4; ii++) {
                    int idx = lane + 32 * ii;
                    if (idx < 98) {
                        float2 cs = s_cs[kki[ii]];
                        int2   pq = s_pq[kki[ii]];
                        int col = rowi[ii];
                        float a1 = sf[pq.x*RS + col];
                        float a2 = sf[pq.y*RS + col];
                        sf[pq.x*RS + col] = cs.x * a1 - cs.y * a2;
                        sf[pq.y*RS + col] = fmaf(cs.y, a1, cs.x * a2);
                    }
                }
                __syncwarp();
            }
        }
        // top-5 eigenvalues ascending via parallel rank
        float ev = (lane < 14) ? sf[lane * (RS+1)] : 1e30f;
        int rank = 0;
        #pragma unroll
        for (int j2 = 0; j2 < 14; j2++) {
            float evj = sf[j2 * (RS+1)];
            rank += (evj < ev || (evj == ev && j2 < lane)) ? 1 : 0;
        }
        if (lane < 14 && rank >= 9) s_comb[rank - 9] = ev;
    }
    __syncthreads();

    // ---- classifier: 37 -> 64 (elu) -> 32 (elu) -> 2 ----
    if (tid < 64) {
        float a = c1_b[tid];
        #pragma unroll
        for (int i = 0; i < 37; i++)
            a = fmaf(s_comb[i], c1_w[i * 64 + tid], a);
        s_b1[tid] = elu(a);
    }
    __syncthreads();
    if (tid < 32) {
        float a2 = c2_b[lane];
        #pragma unroll
        for (int i = 0; i < 64; i++)
            a2 = fmaf(s_b1[i], c2_w[i * 32 + lane], a2);
        float h2 = elu(a2);
        float r0 = warp_sum(h2 * c3_w[lane * 2 + 0]);
        float r1 = warp_sum(h2 * c3_w[lane * 2 + 1]);
        if (lane == 0) {
            out[b * 2 + 0] = r0 + c3_b[0];
            out[b * 2 + 1] = r1 + c3_b[1];
        }
    }
}

extern "C" void kernel_launch(void* const* d_in, const int* in_sizes, int n_in,
                              void* d_out, int out_size)
{
    const float* ws     = (const float*)d_in[0];
    const float* gate_w = (const float*)d_in[1];
    const float* gate_b = (const float*)d_in[2];
    const float* gcn_w  = (const float*)d_in[3];
    const float* gcn_b  = (const float*)d_in[4];
    const float* ln_g   = (const float*)d_in[5];
    const float* ln_b   = (const float*)d_in[6];
    const float* attn_w = (const float*)d_in[7];
    const float* attn_b = (const float*)d_in[8];
    const float* c1_w   = (const float*)d_in[9];
    const float* c1_b   = (const float*)d_in[10];
    const float* c2_w   = (const float*)d_in[11];
    const float* c2_b   = (const float*)d_in[12];
    const float* c3_w   = (const float*)d_in[13];
    const float* c3_b   = (const float*)d_in[14];
    float* out = (float*)d_out;

    tgsm_fused<<<Bn, 128>>>(ws, gate_w, gate_b, gcn_w, gcn_b, ln_g, ln_b,
                            attn_w, attn_b, c1_w, c1_b, c2_w, c2_b,
                            c3_w, c3_b, out);
}

// round 17
// speedup vs baseline: 1.0153x; 1.0153x over previous
#include <cuda_runtime.h>
#include <cuda_bf16.h>

// TGSM v17: v15 (CH=16, 7 CTAs/SM) with packed broadcast loads in the task
// phase: dis read as float4 groups, Gram rows as float4+float, mr pairs
// packed two-nodes-per-float4. Zero global scratch.
// B=1024, T=256, N=14, Fd=4, H=32, K=5, C=2

#define Bn 1024
#define Tn 256
#define Nn 14
#define Hn 32
#define CH 16          // chunk length (t steps per chunk)
#define RS 20          // row stride (floats) in the esm matrix

__device__ __forceinline__ float warp_sum(float v) {
    v += __shfl_xor_sync(0xffffffffu, v, 16);
    v += __shfl_xor_sync(0xffffffffu, v, 8);
    v += __shfl_xor_sync(0xffffffffu, v, 4);
    v += __shfl_xor_sync(0xffffffffu, v, 2);
    v += __shfl_xor_sync(0xffffffffu, v, 1);
    return v;
}
__device__ __forceinline__ float elu(float y) {
    return (y > 0.0f) ? y : (__expf(y) - 1.0f);
}
__device__ __forceinline__ float sigmoid_fast(float x) {
    float th;
    asm("tanh.approx.f32 %0, %1;" : "=f"(th) : "f"(0.5f * x));
    return fmaf(0.5f, th, 0.5f);
}
// map edge index e (0..90) to pair (n<m), row-major over upper triangle
__device__ __forceinline__ void edge_map(int e, int& n_, int& m_) {
    int n = 0, r = e, rl = 13;
    while (n < 13 && r >= rl) { r -= rl; rl--; n++; }
    n_ = n; m_ = n + 1 + r;
}

__global__ __launch_bounds__(128, 7)
void tgsm_fused(const float* __restrict__ ws,
                const float* __restrict__ gate_w, const float* __restrict__ gate_b,
                const float* __restrict__ gcn_w,  const float* __restrict__ gcn_b,
                const float* __restrict__ ln_g,   const float* __restrict__ ln_b,
                const float* __restrict__ attn_w, const float* __restrict__ attn_b,
                const float* __restrict__ c1_w,   const float* __restrict__ c1_b,
                const float* __restrict__ c2_w,   const float* __restrict__ c2_b,
                const float* __restrict__ c3_w,   const float* __restrict__ c3_b,
                float* __restrict__ out)
{
    const int b    = blockIdx.x;
    const int tid  = threadIdx.x;
    const int lane = tid & 31;
    const int warp = tid >> 5;
    const int half = lane >> 4;    // dual-task half
    const int c    = lane & 15;    // node index within half
    const int cc   = (c < 14) ? c : 0;

    __shared__ __align__(16) float4 s_nrm[CH][17];       // padded
    __shared__ float  s_len[CH][16];
    __shared__ __align__(16) float s_esmF[CH][Nn * RS];  // full sym matrices
    __shared__ __align__(16) float4 s_q[4][2][16];
    __shared__ __align__(16) float  s_dis[4][2][16];     // read as float4 groups
    __shared__ float4 s_xp[4][2][17];                     // padded
    __shared__ __align__(16) float2 s_mr[4][2][16];      // read as float4 pairs
    __shared__ __align__(16) float4 s_Gr4[5];            // Gram row i, cols 0..3
    __shared__ float  s_Gr1[5];                          // Gram row i, col 4
    __shared__ float4 s_SWb4;                            // SWb[0..3]
    __shared__ float  s_SWb1;                            // SWb[4]
    __shared__ float  s_pool[4][Hn];
    __shared__ float2 s_MS[4];
    __shared__ float2 s_cs[7];
    __shared__ int2   s_pq[7];
    __shared__ float  s_comb[5 + Hn];
    __shared__ float  s_b1[64];

    // constants (all warps run all phases)
    const float gw0 = gate_w[0], gw1 = gate_w[1], gbv = gate_b[0];
    const float Wc0 = gcn_w[0*Hn + lane];
    const float Wc1 = gcn_w[1*Hn + lane];
    const float Wc2 = gcn_w[2*Hn + lane];
    const float Wc3 = gcn_w[3*Hn + lane];
    const float gcnb = gcn_b[lane];
    const float lng = ln_g[lane], lnb = ln_b[lane];
    const float awv = attn_w[lane], attnb = attn_b[0];

    if (warp == 0) {
        float vW[5] = {Wc0, Wc1, Wc2, Wc3, gcnb};
        #pragma unroll
        for (int i2 = 0; i2 < 5; i2++) {
            float g0 = warp_sum(vW[i2] * vW[0]);
            float g1 = warp_sum(vW[i2] * vW[1]);
            float g2 = warp_sum(vW[i2] * vW[2]);
            float g3 = warp_sum(vW[i2] * vW[3]);
            float g4 = warp_sum(vW[i2] * vW[4]);
            if (lane == 0) {
                s_Gr4[i2] = make_float4(g0, g1, g2, g3);
                s_Gr1[i2] = g4;
            }
        }
        float sw0 = warp_sum(vW[0]);
        float sw1 = warp_sum(vW[1]);
        float sw2 = warp_sum(vW[2]);
        float sw3 = warp_sum(vW[3]);
        float sw4 = warp_sum(vW[4]);
        if (lane == 0) {
            s_SWb4 = make_float4(sw0, sw1, sw2, sw3);
            s_SWb1 = sw4;
        }
    }
    // zero ALL CH*Nn diagonal entries ONCE (strided; never overwritten after)
    for (int i = tid; i < CH * Nn; i += 128) {
        int k2 = i / Nn, d = i - k2 * Nn;
        s_esmF[k2][d * (RS + 1)] = 0.0f;
    }
    // zero the dis tail slots (read as part of float4 group, never used in math
    // but keep deterministic)
    if (warp < 4 && lane < 2) {
        s_dis[warp][0][14 + lane] = 0.0f;
        s_dis[warp][1][14 + lane] = 0.0f;
    }

    // recurrence edge (tid-based)
    int rn = 0, rm = 1;
    const bool ract = (tid < 91);
    if (ract) edge_map(tid, rn, rm);
    float ee = 0.0f;

    // per-warp online softmax state (lane = channel)
    float Pol = 0.0f, Mol = -1e30f, Sol = 0.0f;

    const float4* src = reinterpret_cast<const float4*>(ws) + (size_t)b * (Tn * Nn);

    for (int ch = 0; ch < Tn / CH; ch++) {
        const int t0 = ch * CH;
        __syncthreads();     // protects s_nrm/s_esmF reuse (+ init first iter)

        // ---- cooperative load + normalize: CH steps x 14 nodes ----
        #pragma unroll
        for (int r2 = 0; r2 < 2; r2++) {
            int off = r2 * 128 + tid;
            if (off < CH * Nn) {
                float4 v = src[t0 * Nn + off];
                float d2 = v.x*v.x + v.y*v.y + v.z*v.z + v.w*v.w;
                float inv = rsqrtf(fmaxf(d2, 1e-24f));
                int tl2 = off / 14;
                int nd  = off - tl2 * 14;
                s_nrm[tl2][nd] = make_float4(v.x*inv, v.y*inv, v.z*inv, v.w*inv);
                s_len[tl2][nd] = d2 * inv;   // = |de|
            }
        }
        __syncthreads();

        // ---- edge recurrence: CH steps, write symmetric matrix ----
        if (ract) {
            #pragma unroll 4
            for (int k = 0; k < CH; k++) {
                float4 a  = s_nrm[k][rn];
                float4 c4 = s_nrm[k][rm];
                float dot = a.x * c4.x;
                dot = fmaf(a.y, c4.y, dot);
                dot = fmaf(a.z, c4.z, dot);
                dot = fmaf(a.w, c4.w, dot);
                float adj = fmaf(dot, 0.5f, 0.5f);
                float xg = fmaf(gw0, ee, fmaf(gw1, adj, gbv));
                float z  = sigmoid_fast(xg);
                ee = fmaf(z, adj - ee, ee);
                s_esmF[k][rn * RS + rm] = ee;
                s_esmF[k][rm * RS + rn] = ee;
            }
        }
        __syncthreads();

        // ---- tasks: 2 rounds, dual-task half-warps, merged A+B phase ----
        #pragma unroll 1
        for (int j = 0; j < 2; j++) {
            const int tl = 8 * j + 2 * warp + half;
            const float* rowp = &s_esmF[tl][cc * RS];
            const bool act = (c < 14);

            // load row ONCE (vectorized, conflict-free) into registers
            float4 e0 = *reinterpret_cast<const float4*>(rowp);
            float4 e1 = *reinterpret_cast<const float4*>(rowp + 4);
            float4 e2 = *reinterpret_cast<const float4*>(rowp + 8);
            float2 e3 = *reinterpret_cast<const float2*>(rowp + 12);
            float er[14] = {e0.x,e0.y,e0.z,e0.w, e1.x,e1.y,e1.z,e1.w,
                            e2.x,e2.y,e2.z,e2.w, e3.x,e3.y};

            // rowsum -> dis, q ; publish for the matvec broadcast
            float rs = 1.0f;
            #pragma unroll
            for (int m3 = 0; m3 < 14; m3++) rs += er[m3];
            float dis = rsqrtf(fmaxf(rs, 1e-6f));
            float4 nr = s_nrm[tl][cc];
            float f = s_len[tl][cc] * dis;
            float4 qreg = make_float4(nr.x*f, nr.y*f, nr.z*f, nr.w*f);
            if (act) {
                s_q[warp][half][c]   = qreg;
                s_dis[warp][half][c] = dis;
            }
            __syncwarp();

            // matvec: q per node, dis in packed float4 groups (18 loads vs 28)
            float4 p = make_float4(0.f,0.f,0.f,0.f);
            float racc = 0.0f;
            {
                const float* db = s_dis[warp][half];
                #define MV(MQ, DM) { \
                    float4 qm = s_q[warp][half][MQ]; \
                    float em  = er[MQ]; \
                    p.x = fmaf(em, qm.x, p.x); \
                    p.y = fmaf(em, qm.y, p.y); \
                    p.z = fmaf(em, qm.z, p.z); \
                    p.w = fmaf(em, qm.w, p.w); \
                    racc = fmaf(em, (DM), racc); }
                float4 dv = *reinterpret_cast<const float4*>(db);
                MV(0, dv.x) MV(1, dv.y) MV(2, dv.z) MV(3, dv.w)
                dv = *reinterpret_cast<const float4*>(db + 4);
                MV(4, dv.x) MV(5, dv.y) MV(6, dv.z) MV(7, dv.w)
                dv = *reinterpret_cast<const float4*>(db + 8);
                MV(8, dv.x) MV(9, dv.y) MV(10, dv.z) MV(11, dv.w)
                dv = *reinterpret_cast<const float4*>(db + 12);
                MV(12, dv.x) MV(13, dv.y)
                #undef MV
            }

            // LN stats (closed form, packed coefficient loads) + publish xp/mr
            if (act) {
                float rr = dis * (racc + dis);
                float x0 = (p.x + qreg.x) * dis;
                float x1 = (p.y + qreg.y) * dis;
                float x2 = (p.z + qreg.z) * dis;
                float x3 = (p.w + qreg.w) * dis;
                float4 sw4 = s_SWb4;
                float mu = (x0*sw4.x + x1*sw4.y + x2*sw4.z + x3*sw4.w
                          + rr*s_SWb1) * (1.0f/32.0f);
                float xt[5] = {x0, x1, x2, x3, rr};
                float s2 = 0.0f;
                #pragma unroll
                for (int ii = 0; ii < 5; ii++) {
                    float4 gr = s_Gr4[ii];
                    float rowd = fmaf(gr.x, x0,
                                 fmaf(gr.y, x1,
                                 fmaf(gr.z, x2,
                                 fmaf(gr.w, x3, s_Gr1[ii] * rr))));
                    s2 = fmaf(xt[ii], rowd, s2);
                }
                s2 *= (1.0f/32.0f);
                float var  = fmaf(-mu, mu, s2);
                float istd = rsqrtf(var + 1e-5f);
                s_xp[warp][half][c] = make_float4(x0*istd, x1*istd, x2*istd, x3*istd);
                s_mr[warp][half][c] = make_float2(rr*istd, mu*istd);
            }
            __syncwarp();

            // phase C: LN apply + ELU + node mean, BOTH tasks; mr packed 2/load
            float acc0 = 0.0f, acc1 = 0.0f;
            {
                const float2* mrA = s_mr[warp][0];
                const float2* mrB = s_mr[warp][1];
                #pragma unroll
                for (int p2 = 0; p2 < 7; p2++) {
                    float4 mA = *reinterpret_cast<const float4*>(mrA + 2*p2);
                    float4 mB = *reinterpret_cast<const float4*>(mrB + 2*p2);
                    #pragma unroll
                    for (int e2i = 0; e2i < 2; e2i++) {
                        int nq = 2*p2 + e2i;
                        float rrA = e2i ? mA.z : mA.x;
                        float muA = e2i ? mA.w : mA.y;
                        float rrB = e2i ? mB.z : mB.x;
                        float muB = e2i ? mB.w : mB.y;
                        float4 xa = s_xp[warp][0][nq];
                        float4 xb = s_xp[warp][1][nq];
                        float ha = -muA;
                        ha = fmaf(xa.x, Wc0, ha);
                        ha = fmaf(xa.y, Wc1, ha);
                        ha = fmaf(xa.z, Wc2, ha);
                        ha = fmaf(xa.w, Wc3, ha);
                        ha = fmaf(rrA, gcnb, ha);
                        acc0 += elu(fmaf(ha, lng, lnb));
                        float hb = -muB;
                        hb = fmaf(xb.x, Wc0, hb);
                        hb = fmaf(xb.y, Wc1, hb);
                        hb = fmaf(xb.z, Wc2, hb);
                        hb = fmaf(xb.w, Wc3, hb);
                        hb = fmaf(rrB, gcnb, hb);
                        acc1 += elu(fmaf(hb, lng, lnb));
                    }
                }
            }
            float ge0 = acc0 * (1.0f / 14.0f);
            float ge1 = acc1 * (1.0f / 14.0f);

            // merged dual-score online softmax update (exact)
            float r0 = warp_sum(ge0 * awv);
            float r1 = warp_sum(ge1 * awv);
            float sc0 = r0 + attnb, sc1 = r1 + attnb;
            float nM = fmaxf(Mol, fmaxf(sc0, sc1));
            float al = __expf(Mol - nM);
            float w0 = __expf(sc0 - nM);
            float w1 = __expf(sc1 - nM);
            Pol = fmaf(Pol, al, fmaf(w0, ge0, w1 * ge1));
            Sol = fmaf(Sol, al, w0 + w1);
            Mol = nM;
            __syncwarp();
        }
    }

    // ---- publish per-warp pool state ----
    s_pool[warp][lane] = Pol;
    if (lane == 0) s_MS[warp] = make_float2(Mol, Sol);
    __syncthreads();
    // final esm matrix: s_esmF[CH-1] (t=255), symmetric, zero diag. Ready.

    if (warp == 0) {
        // ---- combine 4 online-softmax partials (exact) ----
        float2 ms0 = s_MS[0], ms1 = s_MS[1], ms2 = s_MS[2], ms3 = s_MS[3];
        float M = fmaxf(fmaxf(ms0.x, ms1.x), fmaxf(ms2.x, ms3.x));
        float f0 = __expf(ms0.x - M), f1 = __expf(ms1.x - M);
        float f2 = __expf(ms2.x - M), f3 = __expf(ms3.x - M);
        float P = s_pool[0][lane]*f0 + s_pool[1][lane]*f1
                + s_pool[2][lane]*f2 + s_pool[3][lane]*f3;
        float S = ms0.y*f0 + ms1.y*f1 + ms2.y*f2 + ms3.y*f3;
        s_comb[5 + lane] = __fdividef(P, S);
    } else if (warp == 3) {
        // ---- warp-local parallel Jacobi on s_esmF[CH-1]: 6 sweeps ----
        float* sf = s_esmF[CH - 1];
        int rowi[4], kki[4];
        #pragma unroll
        for (int ii = 0; ii < 4; ii++) {
            int idx = lane + 32 * ii;
            rowi[ii] = idx / 7;
            kki[ii]  = idx - rowi[ii] * 7;
        }
        for (int sweep = 0; sweep < 6; sweep++) {
            for (int r = 0; r < 13; r++) {
                if (lane < 7) {
                    int pj = (lane == 0) ? 0 : 1 + (lane - 1 + r) % 13;
                    int qj = 1 + (12 - lane + r) % 13;
                    float apq = sf[pj*RS + qj];
                    float app = sf[pj*(RS+1)];
                    float aqq = sf[qj*(RS+1)];
                    float ap  = fabsf(apq);
                    float den = (ap > 1e-20f) ? apq : 1.0f;
                    float theta = __fdividef(0.5f * (aqq - app), den);
                    float tt = __fdividef(1.0f, fabsf(theta) + sqrtf(fmaf(theta, theta, 1.0f)));
                    tt = (theta < 0.0f) ? -tt : tt;
                    tt = (ap > 1e-20f) ? tt : 0.0f;
                    float cqq = rsqrtf(fmaf(tt, tt, 1.0f));
                    s_cs[lane] = make_float2(cqq, tt * cqq);
                    s_pq[lane] = make_int2(pj, qj);
                }
                __syncwarp();
                #pragma unroll
                for (int ii = 0; ii < 4; ii++) {
                    int idx = lane + 32 * ii;
                    if (idx < 98) {
                        float2 cs = s_cs[kki[ii]];
                        int2   pq = s_pq[kki[ii]];
                        int row = rowi[ii];
                        float a1 = sf[row*RS + pq.x];
                        float a2 = sf[row*RS + pq.y];
                        sf[row*RS + pq.x] = cs.x * a1 - cs.y * a2;
                        sf[row*RS + pq.y] = fmaf(cs.y, a1, cs.x * a2);
                    }
                }
                __syncwarp();
                #pragma unroll
                for (int ii = 0; ii < 4; ii++) {
                    int idx = lane + 32 * ii;
                    if (idx < 98) {
                        float2 cs = s_cs[kki[ii]];
                        int2   pq = s_pq[kki[ii]];
                        int col = rowi[ii];
                        float a1 = sf[pq.x*RS + col];
                        float a2 = sf[pq.y*RS + col];
                        sf[pq.x*RS + col] = cs.x * a1 - cs.y * a2;
                        sf[pq.y*RS + col] = fmaf(cs.y, a1, cs.x * a2);
                    }
                }
                __syncwarp();
            }
        }
        // top-5 eigenvalues ascending via parallel rank
        float ev = (lane < 14) ? sf[lane * (RS+1)] : 1e30f;
        int rank = 0;
        #pragma unroll
        for (int j2 = 0; j2 < 14; j2++) {
            float evj = sf[j2 * (RS+1)];
            rank += (evj < ev || (evj == ev && j2 < lane)) ? 1 : 0;
        }
        if (lane < 14 && rank >= 9) s_comb[rank - 9] = ev;
    }
    __syncthreads();

    // ---- classifier: 37 -> 64 (elu) -> 32 (elu) -> 2 ----
    if (tid < 64) {
        float a = c1_b[tid];
        #pragma unroll
        for (int i = 0; i < 37; i++)
            a = fmaf(s_comb[i], c1_w[i * 64 + tid], a);
        s_b1[tid] = elu(a);
    }
    __syncthreads();
    if (tid < 32) {
        float a2 = c2_b[lane];
        #pragma unroll
        for (int i = 0; i < 64; i++)
            a2 = fmaf(s_b1[i], c2_w[i * 32 + lane], a2);
        float h2 = elu(a2);
        float r0 = warp_sum(h2 * c3_w[lane * 2 + 0]);
        float r1 = warp_sum(h2 * c3_w[lane * 2 + 1]);
        if (lane == 0) {
            out[b * 2 + 0] = r0 + c3_b[0];
            out[b * 2 + 1] = r1 + c3_b[1];
        }
    }
}

extern "C" void kernel_launch(void* const* d_in, const int* in_sizes, int n_in,
                              void* d_out, int out_size)
{
    const float* ws     = (const float*)d_in[0];
    const float* gate_w = (const float*)d_in[1];
    const float* gate_b = (const float*)d_in[2];
    const float* gcn_w  = (const float*)d_in[3];
    const float* gcn_b  = (const float*)d_in[4];
    const float* ln_g   = (const float*)d_in[5];
    const float* ln_b   = (const float*)d_in[6];
    const float* attn_w = (const float*)d_in[7];
    const float* attn_b = (const float*)d_in[8];
    const float* c1_w   = (const float*)d_in[9];
    const float* c1_b   = (const float*)d_in[10];
    const float* c2_w   = (const float*)d_in[11];
    const float* c2_b   = (const float*)d_in[12];
    const float* c3_w   = (const float*)d_in[13];
    const float* c3_b   = (const float*)d_in[14];
    float* out = (float*)d_out;

    tgsm_fused<<<Bn, 128>>>(ws, gate_w, gate_b, gcn_w, gcn_b, ln_g, ln_b,
                            attn_w, attn_b, c1_w, c1_b, c2_w, c2_b,
                            c3_w, c3_b, out);
}